// round 16
// baseline (speedup 1.0000x reference)
#include <cuda_runtime.h>
#include <cuda_bf16.h>

// TripletLoss: loss = mean_t relu( ||a_t - p_t + eps||_2 - ||a_t - n_t + eps||_2 + margin )
// embeddings [N, 128] f32, triplet index arrays [T] int32. Output: 1 float.
// PERSISTENT fused kernel (608 CTAs, one wave), ITERS=4 front-batched gathers,
// software-pipelined INDEX prefetch (batch i+1 indices load during batch i
// compute), fence-free atomic finalize.

#define MARGIN 0.5f
#define EPS 1e-6f
#define D 128
#define WARPS_PER_BLOCK 8
#define THREADS (WARPS_PER_BLOCK * 32)
#define ITERS 4

__device__ float g_sum;             // zero at module load; last block resets
__device__ unsigned int g_ticket;   // zero at module load; last block resets

__device__ __forceinline__ unsigned int ticket_acq_rel(unsigned int* p) {
    unsigned int c;
    asm volatile("atom.add.acq_rel.gpu.global.u32 %0, [%1], 1;"
                 : "=r"(c) : "l"(p) : "memory");
    return c;
}

__global__ __launch_bounds__(THREADS, 4) void triplet_kernel(
    const float* __restrict__ emb,
    const int* __restrict__ a_idx,
    const int* __restrict__ p_idx,
    const int* __restrict__ n_idx,
    int T,
    float* __restrict__ out)
{
    const int warp_in_block = threadIdx.x >> 5;
    const int lane = threadIdx.x & 31;
    const int warp_global = blockIdx.x * WARPS_PER_BLOCK + warp_in_block;
    const int n_warps = gridDim.x * WARPS_PER_BLOCK;
    const int stride = n_warps * ITERS;

    float acc = 0.0f;   // lane-0 accumulates hinge values across all batches

    int base = warp_global * ITERS;

    // ---- prologue: load indices for first batch ----
    int ai[ITERS], pi[ITERS], ni[ITERS];
    #pragma unroll
    for (int k = 0; k < ITERS; k++) {
        int t = base + k;
        int tt = (t < T) ? t : 0;
        ai[k] = a_idx[tt];
        pi[k] = p_idx[tt];
        ni[k] = n_idx[tt];
    }

    for (; base < T; base += stride) {
        // ---- issue the 12 data loads for THIS batch immediately ----
        float4 a4[ITERS], p4[ITERS], n4[ITERS];
        #pragma unroll
        for (int k = 0; k < ITERS; k++) {
            a4[k] = ((const float4*)(emb + (size_t)ai[k] * D))[lane];
            p4[k] = ((const float4*)(emb + (size_t)pi[k] * D))[lane];
            n4[k] = ((const float4*)(emb + (size_t)ni[k] * D))[lane];
        }

        // ---- prefetch NEXT batch's indices (overlaps data-load latency
        //      and the compute below; independent of everything above) ----
        const int next_base = base + stride;
        int nai[ITERS], npi[ITERS], nni[ITERS];
        if (next_base < T) {
            #pragma unroll
            for (int k = 0; k < ITERS; k++) {
                int t = next_base + k;
                int tt = (t < T) ? t : 0;
                nai[k] = a_idx[tt];
                npi[k] = p_idx[tt];
                nni[k] = n_idx[tt];
            }
        }

        // ---- per-triplet distance + hinge ----
        #pragma unroll
        for (int k = 0; k < ITERS; k++) {
            bool valid = (base + k) < T;

            float dp0 = a4[k].x - p4[k].x + EPS;
            float dp1 = a4[k].y - p4[k].y + EPS;
            float dp2 = a4[k].z - p4[k].z + EPS;
            float dp3 = a4[k].w - p4[k].w + EPS;
            float sp = dp0 * dp0 + dp1 * dp1 + dp2 * dp2 + dp3 * dp3;

            float dn0 = a4[k].x - n4[k].x + EPS;
            float dn1 = a4[k].y - n4[k].y + EPS;
            float dn2 = a4[k].z - n4[k].z + EPS;
            float dn3 = a4[k].w - n4[k].w + EPS;
            float sn = dn0 * dn0 + dn1 * dn1 + dn2 * dn2 + dn3 * dn3;

            // Fold halves, then split-warp: lanes 0-15 reduce sp, 16-31 reduce sn.
            sp += __shfl_xor_sync(0xFFFFFFFFu, sp, 16);
            sn += __shfl_xor_sync(0xFFFFFFFFu, sn, 16);
            float v = (lane < 16) ? sp : sn;
            #pragma unroll
            for (int off = 8; off > 0; off >>= 1)
                v += __shfl_xor_sync(0xFFFFFFFFu, v, off);

            float r = sqrtf(v);                                  // lane0: d_pos, lane16: d_neg
            float r_other = __shfl_xor_sync(0xFFFFFFFFu, r, 16); // lane0 gets d_neg

            if (lane == 0 && valid) {
                float h = r - r_other + MARGIN;
                acc += (h > 0.0f) ? h : 0.0f;
            }
        }

        // ---- rotate prefetched indices in ----
        if (next_base < T) {
            #pragma unroll
            for (int k = 0; k < ITERS; k++) {
                ai[k] = nai[k];
                pi[k] = npi[k];
                ni[k] = nni[k];
            }
        }
    }

    // ---- block reduction of lane-0 partials, one atomic per block ----
    __shared__ float warp_part[WARPS_PER_BLOCK];
    if (lane == 0) warp_part[warp_in_block] = acc;
    __syncthreads();

    __shared__ bool is_last;
    if (threadIdx.x == 0) {
        float s = 0.0f;
        #pragma unroll
        for (int w = 0; w < WARPS_PER_BLOCK; w++) s += warp_part[w];
        atomicAdd(&g_sum, s);                       // relaxed, L2-coherent
        unsigned int c = ticket_acq_rel(&g_ticket); // release: orders the add above
        is_last = (c == gridDim.x - 1);             // acquire: sees all prior adds
    }
    __syncthreads();

    // ---- last-block finalize (no fences, no extra kernels) ----
    if (is_last && threadIdx.x == 0) {
        float total;
        asm volatile("ld.acquire.gpu.global.f32 %0, [%1];"
                     : "=f"(total) : "l"(&g_sum) : "memory");
        out[0] = total / (float)T;
        g_sum = 0.0f;     // reset for next graph replay (deterministic)
        g_ticket = 0;
    }
}

extern "C" void kernel_launch(void* const* d_in, const int* in_sizes, int n_in,
                              void* d_out, int out_size) {
    const float* emb   = (const float*)d_in[0];
    // d_in[1] = labels (unused; triplets already mined)
    const int* a_idx   = (const int*)d_in[2];
    const int* p_idx   = (const int*)d_in[3];
    const int* n_idx   = (const int*)d_in[4];
    float* out         = (float*)d_out;
    const int T        = in_sizes[2];

    // Persistent one-wave grid: 4 CTAs/SM.
    static int num_sms = 0;
    if (num_sms == 0) {
        cudaDeviceGetAttribute(&num_sms, cudaDevAttrMultiProcessorCount, 0);
        if (num_sms <= 0) num_sms = 148;
    }
    int blocks = num_sms * 4;   // GB300: 152*4 = 608

    triplet_kernel<<<blocks, THREADS>>>(emb, a_idx, p_idx, n_idx, T, out);
}